// round 1
// baseline (speedup 1.0000x reference)
#include <cuda_runtime.h>

// VectorQuantizer: z [32,4096,64] fp32, W [512,64] fp32.
// Outputs concatenated fp32: z_q_st (8388608) | indices-as-float (131072) | loss (1).

#define DIM      64
#define KCODES   512
#define NROWS    131072          // 32*4096
#define THREADS  256
#define GRID     (NROWS / THREADS)   // 512
#define NELEM_ZQ (NROWS * DIM)       // 8388608

__device__ float  g_wsq[KCODES];
__device__ double g_part[GRID];

// ---------------------------------------------------------------------------
// wsq[j] = sum_k fl(W[j][k]^2), sequential add order (mimic jnp.sum(W*W,axis=1))
// ---------------------------------------------------------------------------
__global__ void wsq_kernel(const float* __restrict__ W) {
    int j = blockIdx.x * blockDim.x + threadIdx.x;
    if (j < KCODES) {
        const float* w = W + j * DIM;
        float acc = 0.0f;
        #pragma unroll
        for (int k = 0; k < DIM; k++) {
            float p = __fmul_rn(w[k], w[k]);   // round square first
            acc = __fadd_rn(acc, p);           // then sequential add
        }
        g_wsq[j] = acc;
    }
}

// ---------------------------------------------------------------------------
// Main: one thread per row. W staged in shared (128 KB), broadcast LDS reads.
// ---------------------------------------------------------------------------
__global__ __launch_bounds__(THREADS, 1)
void vq_kernel(const float* __restrict__ z,
               const float* __restrict__ W,
               float* __restrict__ out,
               int out_size) {
    extern __shared__ float smem[];           // [KCODES*DIM] W, then [KCODES] wsq
    float* sW   = smem;
    float* swsq = smem + KCODES * DIM;

    // cooperative, coalesced W load
    for (int idx = threadIdx.x; idx < (KCODES * DIM) / 4; idx += THREADS)
        ((float4*)sW)[idx] = ((const float4*)W)[idx];
    for (int idx = threadIdx.x; idx < KCODES; idx += THREADS)
        swsq[idx] = g_wsq[idx];
    __syncthreads();

    const int row = blockIdx.x * THREADS + threadIdx.x;
    const float* zr = z + (size_t)row * DIM;

    // z row into registers
    float zv[DIM];
    #pragma unroll
    for (int k = 0; k < DIM; k += 4) {
        float4 v = *(const float4*)(zr + k);
        zv[k] = v.x; zv[k+1] = v.y; zv[k+2] = v.z; zv[k+3] = v.w;
    }

    // zz = sum_k fl(z_k^2), sequential (mimic jnp.sum(z*z,axis=1))
    float zz = 0.0f;
    #pragma unroll
    for (int k = 0; k < DIM; k++)
        zz = __fadd_rn(zz, __fmul_rn(zv[k], zv[k]));

    float bestDist = 3.0e38f;
    int   bestIdx  = 0;

    // 8 codes at a time, k ascending sequential fmaf per code (mimic gemm k-loop)
    #pragma unroll 1
    for (int j0 = 0; j0 < KCODES; j0 += 8) {
        float acc[8];
        #pragma unroll
        for (int jj = 0; jj < 8; jj++) acc[jj] = 0.0f;

        #pragma unroll
        for (int k = 0; k < DIM; k += 4) {
            #pragma unroll
            for (int jj = 0; jj < 8; jj++) {
                const float4 w4 = *(const float4*)(sW + (j0 + jj) * DIM + k);
                acc[jj] = __fmaf_rn(zv[k    ], w4.x, acc[jj]);
                acc[jj] = __fmaf_rn(zv[k + 1], w4.y, acc[jj]);
                acc[jj] = __fmaf_rn(zv[k + 2], w4.z, acc[jj]);
                acc[jj] = __fmaf_rn(zv[k + 3], w4.w, acc[jj]);
            }
        }

        #pragma unroll
        for (int jj = 0; jj < 8; jj++) {
            // dist = fl( fl(zz + wsq) - fl(2*dot) ), exactly A + B - 2C
            float s    = __fadd_rn(zz, swsq[j0 + jj]);
            float dist = __fsub_rn(s, __fmul_rn(2.0f, acc[jj]));
            if (dist < bestDist) { bestDist = dist; bestIdx = j0 + jj; }
        }
    }

    // z_q_st = fl(z + fl(w - z));  loss term = fl(z - z_q_st)^2
    const float* wb = sW + bestIdx * DIM;
    float lsum = 0.0f;
    #pragma unroll
    for (int k = 0; k < DIM; k += 4) {
        float4 o;
        float q, st, df;
        q = wb[k    ]; st = __fadd_rn(zv[k    ], __fsub_rn(q, zv[k    ])); o.x = st;
        df = __fsub_rn(zv[k    ], st); lsum = __fadd_rn(lsum, __fmul_rn(df, df));
        q = wb[k + 1]; st = __fadd_rn(zv[k + 1], __fsub_rn(q, zv[k + 1])); o.y = st;
        df = __fsub_rn(zv[k + 1], st); lsum = __fadd_rn(lsum, __fmul_rn(df, df));
        q = wb[k + 2]; st = __fadd_rn(zv[k + 2], __fsub_rn(q, zv[k + 2])); o.z = st;
        df = __fsub_rn(zv[k + 2], st); lsum = __fadd_rn(lsum, __fmul_rn(df, df));
        q = wb[k + 3]; st = __fadd_rn(zv[k + 3], __fsub_rn(q, zv[k + 3])); o.w = st;
        df = __fsub_rn(zv[k + 3], st); lsum = __fadd_rn(lsum, __fmul_rn(df, df));
        *(float4*)(out + (size_t)row * DIM + k) = o;
    }

    // indices (as float) after z_q block
    if (out_size > NELEM_ZQ + row)
        out[NELEM_ZQ + row] = (float)bestIdx;

    // deterministic block-level loss reduction
    __shared__ double red[THREADS];
    red[threadIdx.x] = (double)lsum;
    __syncthreads();
    #pragma unroll
    for (int s = THREADS / 2; s > 0; s >>= 1) {
        if (threadIdx.x < s) red[threadIdx.x] += red[threadIdx.x + s];
        __syncthreads();
    }
    if (threadIdx.x == 0) g_part[blockIdx.x] = red[0];
}

// ---------------------------------------------------------------------------
// Final loss: sequential deterministic sum of 512 block partials
// ---------------------------------------------------------------------------
__global__ void loss_kernel(float* __restrict__ out, int out_size) {
    if (threadIdx.x == 0 && blockIdx.x == 0) {
        double t = 0.0;
        for (int i = 0; i < GRID; i++) t += g_part[i];
        float loss = (float)(0.25 * t / (double)((size_t)NROWS * DIM));
        int loss_pos = NELEM_ZQ + NROWS;
        if (out_size > loss_pos) out[loss_pos] = loss;
    }
}

extern "C" void kernel_launch(void* const* d_in, const int* in_sizes, int n_in,
                              void* d_out, int out_size) {
    const float* z = (const float*)d_in[0];
    const float* W = (const float*)d_in[1];
    float* out = (float*)d_out;

    size_t smem = (size_t)(KCODES * DIM + KCODES) * sizeof(float);
    static bool attr_set = false;
    if (!attr_set) {
        cudaFuncSetAttribute(vq_kernel, cudaFuncAttributeMaxDynamicSharedMemorySize,
                             (int)smem);
        attr_set = true;
    }

    wsq_kernel<<<1, KCODES>>>(W);
    vq_kernel<<<GRID, THREADS, smem>>>(z, W, out, out_size);
    loss_kernel<<<1, 32>>>(out, out_size);
}